// round 2
// baseline (speedup 1.0000x reference)
#include <cuda_runtime.h>
#include <cstdint>
#include <math_constants.h>

// MiniRocket fused dilated-conv + max/ppv. fp32 packed-FFMA2, direct-LDG design.
// x[16,12,5000], W[10,1000,12,9] ternary, bias[10,1000] -> out[16, 20000].
//
// Stage 1 (prep): zero-padded x copy in __device__ global (pad 2048 = 4*maxdil)
//   -> all tap loads are unguarded and 16B-aligned for d >= 4.
// Stage 2 (conv_big, d in {4..512}): CTA=(jtile,b,di). 320 thr = 20 jgroups x
//   16 tgroups. Thread: 2 kernels x 8 timesteps. Inner (c,k): 2x LDG.128 (as
//   ulonglong2), 2x LDS.64 (pre-duplicated w), 8x fma.rn.f32x2. No syncs.
// Stage 3 (conv_small<D>, d in {1,2}): 24-float register window per channel,
//   packs CSE'd across taps.

#define L        5000
#define PAD      2048
#define ROWLEN   (PAD + L + PAD)     // 9096 floats per (b,c) row
#define NROWS    (16 * 12)
#define JB       40                  // kernels per CTA
#define NTHREADS 320                 // 20 jgroups x 16 tgroups
#define TG       16

typedef unsigned long long u64;

__device__ __align__(16) float g_xpad[NROWS * ROWLEN];   // ~7 MB scratch

__device__ __forceinline__ u64 pk2(float lo, float hi) {
    u64 r;
    asm("mov.b64 %0, {%1, %2};" : "=l"(r) : "f"(lo), "f"(hi));
    return r;
}
__device__ __forceinline__ void upk2(float& lo, float& hi, u64 v) {
    asm("mov.b64 {%0, %1}, %2;" : "=f"(lo), "=f"(hi) : "l"(v));
}
__device__ __forceinline__ void ffma2(u64& d, u64 a, u64 b) {
    asm("fma.rn.f32x2 %0, %1, %2, %0;" : "+l"(d) : "l"(a), "l"(b));
}

// ---------------- prep: build zero-padded x ----------------
__global__ void prep_kernel(const float* __restrict__ x) {
    const int G = NROWS * (ROWLEN / 4);
    int i = blockIdx.x * 256 + threadIdx.x;
    if (i >= G) return;
    int row = i / (ROWLEN / 4);
    int p   = (i % (ROWLEN / 4)) * 4;
    float4 v = make_float4(0.f, 0.f, 0.f, 0.f);
    if (p >= PAD && p < PAD + L)
        v = *reinterpret_cast<const float4*>(x + (size_t)row * L + (p - PAD));
    *reinterpret_cast<float4*>(g_xpad + (size_t)row * ROWLEN + p) = v;
}

// ---------------- big dilations: d = 4 << z ----------------
__global__ void __launch_bounds__(NTHREADS, 2)
conv_big(const float* __restrict__ W, const float* __restrict__ bias,
         float* __restrict__ out)
{
    const int jt = blockIdx.x;          // 0..24
    const int b  = blockIdx.y;          // 0..15
    const int zi = blockIdx.z;          // 0..7
    const int di = zi + 2;
    const int d  = 4 << zi;

    __shared__ u64 wdup[JB * 108];
    const float* Wd = W + (size_t)(di * 1000 + jt * JB) * 108;
    for (int e = threadIdx.x; e < JB * 108; e += NTHREADS) {
        float w = Wd[e];
        wdup[e] = pk2(w, w);
    }
    __syncthreads();

    const int jg = threadIdx.x >> 4;    // 0..19
    const int tg = threadIdx.x & 15;    // 0..15
    const int jl = jg * 2;

    const float bv0 = bias[di * 1000 + jt * JB + jl];
    const float bv1 = bias[di * 1000 + jt * JB + jl + 1];
    const float* xb = g_xpad + (size_t)b * 12 * ROWLEN + PAD;
    const u64* wq0b = wdup + (size_t)jl * 108;
    const u64* wq1b = wdup + (size_t)(jl + 1) * 108;

    float m0 = -CUDART_INF_F, m1 = -CUDART_INF_F;
    int   c0 = 0, c1 = 0;

    for (int t = tg * 8; t < L; t += TG * 8) {
        u64 a00 = 0, a01 = 0, a02 = 0, a03 = 0;
        u64 a10 = 0, a11 = 0, a12 = 0, a13 = 0;

#pragma unroll 1
        for (int c = 0; c < 12; c++) {
            const float* pc = xb + c * ROWLEN + t;
            const u64* wq0 = wq0b + c * 9;
            const u64* wq1 = wq1b + c * 9;
#pragma unroll
            for (int k = 0; k < 9; k++) {
                const float* px = pc + (k - 4) * d;
                ulonglong2 xl = *reinterpret_cast<const ulonglong2*>(px);
                ulonglong2 xh = *reinterpret_cast<const ulonglong2*>(px + 4);
                u64 w0 = wq0[k];
                u64 w1 = wq1[k];
                ffma2(a00, w0, xl.x); ffma2(a01, w0, xl.y);
                ffma2(a02, w0, xh.x); ffma2(a03, w0, xh.y);
                ffma2(a10, w1, xl.x); ffma2(a11, w1, xl.y);
                ffma2(a12, w1, xh.x); ffma2(a13, w1, xh.y);
            }
        }

        float f0, f1;
        upk2(f0, f1, a00); m0 = fmaxf(m0, fmaxf(f0, f1)); c0 += (f0 > bv0) + (f1 > bv0);
        upk2(f0, f1, a01); m0 = fmaxf(m0, fmaxf(f0, f1)); c0 += (f0 > bv0) + (f1 > bv0);
        upk2(f0, f1, a02); m0 = fmaxf(m0, fmaxf(f0, f1)); c0 += (f0 > bv0) + (f1 > bv0);
        upk2(f0, f1, a03); m0 = fmaxf(m0, fmaxf(f0, f1)); c0 += (f0 > bv0) + (f1 > bv0);
        upk2(f0, f1, a10); m1 = fmaxf(m1, fmaxf(f0, f1)); c1 += (f0 > bv1) + (f1 > bv1);
        upk2(f0, f1, a11); m1 = fmaxf(m1, fmaxf(f0, f1)); c1 += (f0 > bv1) + (f1 > bv1);
        upk2(f0, f1, a12); m1 = fmaxf(m1, fmaxf(f0, f1)); c1 += (f0 > bv1) + (f1 > bv1);
        upk2(f0, f1, a13); m1 = fmaxf(m1, fmaxf(f0, f1)); c1 += (f0 > bv1) + (f1 > bv1);
    }

#pragma unroll
    for (int o = 8; o > 0; o >>= 1) {
        m0 = fmaxf(m0, __shfl_xor_sync(0xffffffffu, m0, o));
        m1 = fmaxf(m1, __shfl_xor_sync(0xffffffffu, m1, o));
        c0 += __shfl_xor_sync(0xffffffffu, c0, o);
        c1 += __shfl_xor_sync(0xffffffffu, c1, o);
    }
    if (tg == 0) {
        float* ob = out + (size_t)b * 20000 + di * 2000;
        int j = jt * JB + jl;
        ob[j]        = m0;
        ob[j + 1]    = m1;
        ob[1000 + j]     = (float)c0 * (1.0f / (float)L);
        ob[1000 + j + 1] = (float)c1 * (1.0f / (float)L);
    }
}

// ---------------- small dilations: D in {1,2} ----------------
template <int D>
__global__ void __launch_bounds__(NTHREADS, 2)
conv_small(const float* __restrict__ W, const float* __restrict__ bias,
           float* __restrict__ out)
{
    const int jt = blockIdx.x;
    const int b  = blockIdx.y;
    const int di = (D == 1) ? 0 : 1;

    __shared__ u64 wdup[JB * 108];
    const float* Wd = W + (size_t)(di * 1000 + jt * JB) * 108;
    for (int e = threadIdx.x; e < JB * 108; e += NTHREADS) {
        float w = Wd[e];
        wdup[e] = pk2(w, w);
    }
    __syncthreads();

    const int jg = threadIdx.x >> 4;
    const int tg = threadIdx.x & 15;
    const int jl = jg * 2;

    const float bv0 = bias[di * 1000 + jt * JB + jl];
    const float bv1 = bias[di * 1000 + jt * JB + jl + 1];
    const float* xb = g_xpad + (size_t)b * 12 * ROWLEN + PAD;
    const u64* wq0b = wdup + (size_t)jl * 108;
    const u64* wq1b = wdup + (size_t)(jl + 1) * 108;

    float m0 = -CUDART_INF_F, m1 = -CUDART_INF_F;
    int   c0 = 0, c1 = 0;

    for (int t = tg * 8; t < L; t += TG * 8) {
        u64 a00 = 0, a01 = 0, a02 = 0, a03 = 0;
        u64 a10 = 0, a11 = 0, a12 = 0, a13 = 0;

#pragma unroll 1
        for (int c = 0; c < 12; c++) {
            const float* pc = xb + c * ROWLEN + t;
            float xr[24];
#pragma unroll
            for (int i = 0; i < 6; i++) {
                float4 v = *reinterpret_cast<const float4*>(pc - 8 + 4 * i);
                xr[4 * i + 0] = v.x; xr[4 * i + 1] = v.y;
                xr[4 * i + 2] = v.z; xr[4 * i + 3] = v.w;
            }
            const u64* wq0 = wq0b + c * 9;
            const u64* wq1 = wq1b + c * 9;
#pragma unroll
            for (int k = 0; k < 9; k++) {
                const int s = 8 + (k - 4) * D;          // compile-time
                u64 x0 = pk2(xr[s + 0], xr[s + 1]);     // CSE'd across k
                u64 x1 = pk2(xr[s + 2], xr[s + 3]);
                u64 x2 = pk2(xr[s + 4], xr[s + 5]);
                u64 x3 = pk2(xr[s + 6], xr[s + 7]);
                u64 w0 = wq0[k];
                u64 w1 = wq1[k];
                ffma2(a00, w0, x0); ffma2(a01, w0, x1);
                ffma2(a02, w0, x2); ffma2(a03, w0, x3);
                ffma2(a10, w1, x0); ffma2(a11, w1, x1);
                ffma2(a12, w1, x2); ffma2(a13, w1, x3);
            }
        }

        float f0, f1;
        upk2(f0, f1, a00); m0 = fmaxf(m0, fmaxf(f0, f1)); c0 += (f0 > bv0) + (f1 > bv0);
        upk2(f0, f1, a01); m0 = fmaxf(m0, fmaxf(f0, f1)); c0 += (f0 > bv0) + (f1 > bv0);
        upk2(f0, f1, a02); m0 = fmaxf(m0, fmaxf(f0, f1)); c0 += (f0 > bv0) + (f1 > bv0);
        upk2(f0, f1, a03); m0 = fmaxf(m0, fmaxf(f0, f1)); c0 += (f0 > bv0) + (f1 > bv0);
        upk2(f0, f1, a10); m1 = fmaxf(m1, fmaxf(f0, f1)); c1 += (f0 > bv1) + (f1 > bv1);
        upk2(f0, f1, a11); m1 = fmaxf(m1, fmaxf(f0, f1)); c1 += (f0 > bv1) + (f1 > bv1);
        upk2(f0, f1, a12); m1 = fmaxf(m1, fmaxf(f0, f1)); c1 += (f0 > bv1) + (f1 > bv1);
        upk2(f0, f1, a13); m1 = fmaxf(m1, fmaxf(f0, f1)); c1 += (f0 > bv1) + (f1 > bv1);
    }

#pragma unroll
    for (int o = 8; o > 0; o >>= 1) {
        m0 = fmaxf(m0, __shfl_xor_sync(0xffffffffu, m0, o));
        m1 = fmaxf(m1, __shfl_xor_sync(0xffffffffu, m1, o));
        c0 += __shfl_xor_sync(0xffffffffu, c0, o);
        c1 += __shfl_xor_sync(0xffffffffu, c1, o);
    }
    if (tg == 0) {
        float* ob = out + (size_t)b * 20000 + di * 2000;
        int j = jt * JB + jl;
        ob[j]        = m0;
        ob[j + 1]    = m1;
        ob[1000 + j]     = (float)c0 * (1.0f / (float)L);
        ob[1000 + j + 1] = (float)c1 * (1.0f / (float)L);
    }
}

extern "C" void kernel_launch(void* const* d_in, const int* in_sizes, int n_in,
                              void* d_out, int out_size)
{
    const float* x    = (const float*)d_in[0];  // [16,12,5000]
    const float* W    = (const float*)d_in[1];  // [10,1000,12,9]
    const float* bias = (const float*)d_in[2];  // [10,1000]
    float* out = (float*)d_out;                 // [16,20000]

    const int G = NROWS * (ROWLEN / 4);
    prep_kernel<<<(G + 255) / 256, 256>>>(x);

    dim3 gb(25, 16, 8);
    conv_big<<<gb, NTHREADS>>>(W, bias, out);

    dim3 gs(25, 16, 1);
    conv_small<1><<<gs, NTHREADS>>>(W, bias, out);
    conv_small<2><<<gs, NTHREADS>>>(W, bias, out);
}

// round 4
// speedup vs baseline: 5.1383x; 5.1383x over previous
#include <cuda_runtime.h>
#include <cuda_bf16.h>
#include <cstdint>
#include <math_constants.h>

// MiniRocket via mma.sync (HMMA) bf16 split GEMM — family-agnostic PTX only
// (tcgen05 unavailable: harness compiles at compute_103, not sm_103a).
//
// conv[j,t] = sum_{ck} W[j,ck]*xs[ck,t], xs split into bf16 hi+lo -> K=216 (pad 224).
// CTA = (jtile of 128, batch, dilation). 8 warps; warp w owns j rows [w*16, w*16+16).
// A (W||W, 128x224 bf16) staged once, fragments kept in registers (56 regs).
// Loop 79 chunks of 64 t: B [224 x 64] bf16 row-major SW128 in SMEM (double buf),
// ldmatrix.x4.trans -> col-major B frags; 112 mma.m16n8k16 per warp per chunk;
// fused max / count(>bias) epilogue in registers. No cross-warp reduction.

#define LSEQ    5000
#define PADX    2112
#define ROWLEN  9224            // PADX + LSEQ + PADX (elements, 16B-aligned segs)
#define NCH     12
#define NROWS   192             // 16 batch * 12 ch
#define NCHUNK  79
#define NK      14              // K-steps of 16 (216 -> 224)
#define ASTRIDE 464             // bytes per A row (224 bf16 = 448, +16 pad)

#define AOFF    0
#define ASZ     (128 * ASTRIDE) // 59392
#define B0OFF   ASZ
#define BSZ     (224 * 128)     // 28672 (28 x 1024B atoms)
#define B1OFF   (B0OFF + BSZ)
#define SMEMSZ  (B1OFF + BSZ)   // 116736

typedef unsigned u32;

__device__ __align__(16) __nv_bfloat16 g_xhi[NROWS * ROWLEN];
__device__ __align__(16) __nv_bfloat16 g_xlo[NROWS * ROWLEN];

// ---------------- prep: padded bf16 hi/lo split of x ----------------
__global__ void prep_kernel(const float* __restrict__ x) {
    int p = blockIdx.x * 256 + threadIdx.x;
    int row = blockIdx.y;
    if (p >= ROWLEN) return;
    float v = 0.0f;
    if (p >= PADX && p < PADX + LSEQ) v = x[(size_t)row * LSEQ + (p - PADX)];
    __nv_bfloat16 hi = __float2bfloat16(v);
    __nv_bfloat16 lo = __float2bfloat16(v - __bfloat162float(hi));
    g_xhi[(size_t)row * ROWLEN + p] = hi;
    g_xlo[(size_t)row * ROWLEN + p] = lo;
}

// ---------------- PTX helpers (all baseline, sm_80+) ----------------
__device__ __forceinline__ u32 smem_u32(const void* p) {
    u32 a;
    asm("{ .reg .u64 t; cvta.to.shared.u64 t, %1; cvt.u32.u64 %0, t; }"
        : "=r"(a) : "l"(p));
    return a;
}
__device__ __forceinline__ void ldsm_x4(u32& r0, u32& r1, u32& r2, u32& r3, u32 a) {
    asm volatile("ldmatrix.sync.aligned.m8n8.x4.shared.b16 {%0,%1,%2,%3}, [%4];"
                 : "=r"(r0), "=r"(r1), "=r"(r2), "=r"(r3) : "r"(a));
}
__device__ __forceinline__ void ldsm_x4t(u32& r0, u32& r1, u32& r2, u32& r3, u32 a) {
    asm volatile("ldmatrix.sync.aligned.m8n8.x4.trans.shared.b16 {%0,%1,%2,%3}, [%4];"
                 : "=r"(r0), "=r"(r1), "=r"(r2), "=r"(r3) : "r"(a));
}
__device__ __forceinline__ void mma16816(float* d, const u32* a, u32 b0, u32 b1) {
    asm volatile(
        "mma.sync.aligned.m16n8k16.row.col.f32.bf16.bf16.f32 "
        "{%0,%1,%2,%3}, {%4,%5,%6,%7}, {%8,%9}, {%0,%1,%2,%3};"
        : "+f"(d[0]), "+f"(d[1]), "+f"(d[2]), "+f"(d[3])
        : "r"(a[0]), "r"(a[1]), "r"(a[2]), "r"(a[3]), "r"(b0), "r"(b1));
}

// misaligned 16B load (branch is d-uniform across the CTA)
__device__ __forceinline__ uint4 load16_any(const __nv_bfloat16* p, int d) {
    if (d >= 8) return *reinterpret_cast<const uint4*>(p);
    if (d == 4) {
        const uint2* q = reinterpret_cast<const uint2*>(p);
        uint2 a = q[0], b = q[1];
        return make_uint4(a.x, a.y, b.x, b.y);
    }
    if (d == 2) {
        const u32* q = reinterpret_cast<const u32*>(p);
        return make_uint4(q[0], q[1], q[2], q[3]);
    }
    const unsigned short* s = reinterpret_cast<const unsigned short*>(p);
    return make_uint4((u32)s[0] | ((u32)s[1] << 16), (u32)s[2] | ((u32)s[3] << 16),
                      (u32)s[4] | ((u32)s[5] << 16), (u32)s[6] | ((u32)s[7] << 16));
}

// ---------------- main kernel ----------------
__global__ void __launch_bounds__(256, 1)
mr_hmma(const float* __restrict__ W, const float* __restrict__ bias,
        float* __restrict__ out)
{
    extern __shared__ __align__(1024) char smem[];
    const u32 sb = smem_u32(smem);
    const int tid  = threadIdx.x;
    const int wid  = tid >> 5;
    const int lane = tid & 31;

    const int jt = blockIdx.x;      // 0..7
    const int b  = blockIdx.y;      // 0..15
    const int di = blockIdx.z;      // 0..9
    const int d  = 1 << di;

    // ---- stage A: rows j (128), cols kk (224): W||W in bf16, zero-padded ----
    for (int e = tid; e < 128 * 112; e += 256) {
        int j  = e / 112;
        int kk = (e - j * 112) * 2;       // even; pairs never straddle the 108 seam
        u32 val = 0;
        int jg = jt * 128 + j;
        if (jg < 1000 && kk < 216) {
            int k0 = (kk < 108) ? kk : kk - 108;
            float2 w2 = *reinterpret_cast<const float2*>(
                W + (size_t)(di * 1000 + jg) * 108 + k0);
            __nv_bfloat162 h = __floats2bfloat162_rn(w2.x, w2.y);
            val = *reinterpret_cast<u32*>(&h);
        }
        *reinterpret_cast<u32*>(smem + AOFF + j * ASTRIDE + kk * 2) = val;
    }
    // ---- zero K-pad rows 216..223 (atom 27) of both B buffers, once ----
    for (int e = tid; e < 128; e += 256) {
        int buf = e >> 6, q = e & 63;
        *reinterpret_cast<uint4*>(smem + (buf ? B1OFF : B0OFF) + 27 * 1024 + q * 16)
            = make_uint4(0, 0, 0, 0);
    }

    const __nv_bfloat16* xh = g_xhi + (size_t)b * NCH * ROWLEN;
    const __nv_bfloat16* xl = g_xlo + (size_t)b * NCH * ROWLEN;

    // ---- stage B buffer 0 (chunk 0) ----
    for (int e = tid; e < 216 * 8; e += 256) {
        int row = e >> 3, ch = e & 7;
        int r2 = (row < 108) ? row : row - 108;
        int c = r2 / 9, k = r2 - c * 9;
        const __nv_bfloat16* src = ((row < 108) ? xh : xl)
            + (size_t)c * ROWLEN + (PADX + (k - 4) * d) + ch * 8;
        uint4 v = load16_any(src, d);
        u32 off = (u32)(row >> 3) * 1024u + (u32)(row & 7) * 128u + (u32)ch * 16u;
        off ^= ((u32)(row & 7) << 4);
        *reinterpret_cast<uint4*>(smem + B0OFF + off) = v;
    }
    __syncthreads();

    // ---- load all A fragments into registers (per warp, once) ----
    u32 afr[NK][4];
    {
        u32 abase = sb + AOFF + (u32)(wid * 16 + (lane & 15)) * ASTRIDE
                  + (u32)(lane >> 4) * 16;
#pragma unroll
        for (int q = 0; q < NK; q++)
            ldsm_x4(afr[q][0], afr[q][1], afr[q][2], afr[q][3], abase + q * 32);
    }

    // per-lane B-address components (derived from swizzled row layout)
    const int bm = lane >> 3, br = lane & 7;
    const u32 laneA = (u32)(bm & 1) * 1024u + (u32)br * 128u;
    const u32 laneT = (u32)(bm >> 1) * 16u;
    const u32 laneR = (u32)br << 4;

    // epilogue state: warp owns rows w*16 + q and + q + 8
    const int qd = lane >> 2;
    const int j0w = jt * 128 + wid * 16;
    const int jr0 = j0w + qd, jr1 = j0w + qd + 8;
    const float bv0 = (jr0 < 1000) ? bias[di * 1000 + jr0] : 0.0f;
    const float bv1 = (jr1 < 1000) ? bias[di * 1000 + jr1] : 0.0f;
    float m0 = -CUDART_INF_F, m1 = -CUDART_INF_F;
    int   c0 = 0, c1 = 0;

    for (int i = 0; i < NCHUNK; i++) {
        const u32 bcur = (i & 1) ? B1OFF : B0OFF;

        // ---- stage next chunk into the other buffer (overlaps MMA below) ----
        if (i + 1 < NCHUNK) {
            const u32 bnxt = (i & 1) ? B0OFF : B1OFF;
            const int t0 = (i + 1) * 64;
            for (int e = tid; e < 216 * 8; e += 256) {
                int row = e >> 3, ch = e & 7;
                int r2 = (row < 108) ? row : row - 108;
                int c = r2 / 9, k = r2 - c * 9;
                const __nv_bfloat16* src = ((row < 108) ? xh : xl)
                    + (size_t)c * ROWLEN + (PADX + t0 + (k - 4) * d) + ch * 8;
                uint4 v = load16_any(src, d);
                u32 off = (u32)(row >> 3) * 1024u + (u32)(row & 7) * 128u
                        + (u32)ch * 16u;
                off ^= ((u32)(row & 7) << 4);
                *reinterpret_cast<uint4*>(smem + bnxt + off) = v;
            }
        }

        // ---- compute chunk i: D[16 x 64] per warp in registers ----
        float dacc[8][4];
#pragma unroll
        for (int p = 0; p < 8; p++) {
            dacc[p][0] = 0.f; dacc[p][1] = 0.f; dacc[p][2] = 0.f; dacc[p][3] = 0.f;
        }
        const u32 bb = sb + bcur + laneA;
#pragma unroll
        for (int q = 0; q < NK; q++) {
#pragma unroll
            for (int p = 0; p < 4; p++) {
                u32 b0, b1, b2, b3;
                ldsm_x4t(b0, b1, b2, b3,
                         bb + (u32)q * 2048u + (((u32)p * 32u + laneT) ^ laneR));
                mma16816(dacc[2 * p],     afr[q], b0, b1);
                mma16816(dacc[2 * p + 1], afr[q], b2, b3);
            }
        }

        // ---- fused epilogue (last chunk: only first 8 t valid = n-tile 0) ----
        const int ntmax = (i == NCHUNK - 1) ? 1 : 8;
#pragma unroll
        for (int p = 0; p < 8; p++) {
            if (p < ntmax) {
                m0 = fmaxf(m0, fmaxf(dacc[p][0], dacc[p][1]));
                c0 += (dacc[p][0] > bv0) + (dacc[p][1] > bv0);
                m1 = fmaxf(m1, fmaxf(dacc[p][2], dacc[p][3]));
                c1 += (dacc[p][2] > bv1) + (dacc[p][3] > bv1);
            }
        }
        __syncthreads();
    }

    // ---- reduce across the 4 lanes of each quad (n positions), write out ----
#pragma unroll
    for (int o = 1; o < 4; o <<= 1) {
        m0 = fmaxf(m0, __shfl_xor_sync(0xffffffffu, m0, o));
        m1 = fmaxf(m1, __shfl_xor_sync(0xffffffffu, m1, o));
        c0 += __shfl_xor_sync(0xffffffffu, c0, o);
        c1 += __shfl_xor_sync(0xffffffffu, c1, o);
    }
    if ((lane & 3) == 0) {
        float* ob = out + (size_t)b * 20000 + di * 2000;
        if (jr0 < 1000) { ob[jr0] = m0; ob[1000 + jr0] = (float)c0 * (1.0f / LSEQ); }
        if (jr1 < 1000) { ob[jr1] = m1; ob[1000 + jr1] = (float)c1 * (1.0f / LSEQ); }
    }
}

extern "C" void kernel_launch(void* const* d_in, const int* in_sizes, int n_in,
                              void* d_out, int out_size)
{
    const float* x    = (const float*)d_in[0];  // [16,12,5000]
    const float* W    = (const float*)d_in[1];  // [10,1000,12,9]
    const float* bias = (const float*)d_in[2];  // [10,1000]
    float* out = (float*)d_out;                 // [16,20000]

    dim3 pg((ROWLEN + 255) / 256, NROWS);
    prep_kernel<<<pg, 256>>>(x);

    cudaFuncSetAttribute(mr_hmma, cudaFuncAttributeMaxDynamicSharedMemorySize, SMEMSZ);
    dim3 grid(8, 16, 10);
    mr_hmma<<<grid, 256, SMEMSZ>>>(W, bias, out);
}

// round 6
// speedup vs baseline: 9.3650x; 1.8226x over previous
#include <cuda_runtime.h>
#include <cuda_bf16.h>
#include <cstdint>
#include <math_constants.h>

// MiniRocket via mma.sync (HMMA) bf16 split GEMM, round 6.
// conv[j,t] = W·xhi + W·xlo (same W for both halves -> A is only [128 x 112]).
// 8 pre-shifted padded bf16 copies of xhi/xlo make every tap load an aligned
// LDG.128 for all dilations. SMEM = 2 x 28KB B buffers (A staged through them,
// fragments register-resident) -> 2 CTAs/SM, 16 warps/SM.
// R6 fix: ASTRIDE 232 -> 240 (ldmatrix needs 16B-aligned row addresses).

#define LSEQ    5000
#define PADX    2112
#define ROWLEN  9224            // PADX + LSEQ + PADX
#define NCH     12
#define NROWS   192             // 16 batch * 12 ch
#define NCHUNK  79
#define ASTRIDE 240             // A row stride bytes (112 bf16 = 224 + 16 pad), 16|240

#define BSZ     (224 * 128)     // 28672 bytes (28 SW128 atoms)
#define B0OFF   0
#define B1OFF   BSZ
#define SMEMSZ  (2 * BSZ)       // 57344 (A staging 128*240=30720 fits inside)

typedef unsigned u32;

// 8 shifted copies: XH8[s][row][p] = x[row][p + s - PADX] (zero-padded)
__device__ __align__(16) __nv_bfloat16 g_xhi8[8 * NROWS * ROWLEN];
__device__ __align__(16) __nv_bfloat16 g_xlo8[8 * NROWS * ROWLEN];

// ---------------- prep: padded, hi/lo split, 8 shifts ----------------
__global__ void prep_kernel(const float* __restrict__ x) {
    int p2 = blockIdx.x * 256 + threadIdx.x;   // element-pair index
    if (p2 >= ROWLEN / 2) return;
    int row = blockIdx.y;                      // 0..191
    int s   = blockIdx.z;                      // 0..7
    int p   = p2 * 2;

    float v0 = 0.f, v1 = 0.f;
    int i0 = p + s - PADX, i1 = i0 + 1;
    if (i0 >= 0 && i0 < LSEQ) v0 = x[(size_t)row * LSEQ + i0];
    if (i1 >= 0 && i1 < LSEQ) v1 = x[(size_t)row * LSEQ + i1];

    __nv_bfloat16 h0 = __float2bfloat16(v0);
    __nv_bfloat16 h1 = __float2bfloat16(v1);
    __nv_bfloat16 l0 = __float2bfloat16(v0 - __bfloat162float(h0));
    __nv_bfloat16 l1 = __float2bfloat16(v1 - __bfloat162float(h1));

    size_t o = ((size_t)s * NROWS + row) * ROWLEN + p;
    __nv_bfloat162 hh; hh.x = h0; hh.y = h1;
    __nv_bfloat162 ll; ll.x = l0; ll.y = l1;
    *reinterpret_cast<__nv_bfloat162*>(g_xhi8 + o) = hh;
    *reinterpret_cast<__nv_bfloat162*>(g_xlo8 + o) = ll;
}

// ---------------- PTX helpers (baseline, sm_80+) ----------------
__device__ __forceinline__ u32 smem_u32(const void* p) {
    u32 a;
    asm("{ .reg .u64 t; cvta.to.shared.u64 t, %1; cvt.u32.u64 %0, t; }"
        : "=r"(a) : "l"(p));
    return a;
}
__device__ __forceinline__ void ldsm_x4(u32& r0, u32& r1, u32& r2, u32& r3, u32 a) {
    asm volatile("ldmatrix.sync.aligned.m8n8.x4.shared.b16 {%0,%1,%2,%3}, [%4];"
                 : "=r"(r0), "=r"(r1), "=r"(r2), "=r"(r3) : "r"(a));
}
__device__ __forceinline__ void ldsm_x4t(u32& r0, u32& r1, u32& r2, u32& r3, u32 a) {
    asm volatile("ldmatrix.sync.aligned.m8n8.x4.trans.shared.b16 {%0,%1,%2,%3}, [%4];"
                 : "=r"(r0), "=r"(r1), "=r"(r2), "=r"(r3) : "r"(a));
}
__device__ __forceinline__ void mma16816(float* d, const u32* a, u32 b0, u32 b1) {
    asm volatile(
        "mma.sync.aligned.m16n8k16.row.col.f32.bf16.bf16.f32 "
        "{%0,%1,%2,%3}, {%4,%5,%6,%7}, {%8,%9}, {%0,%1,%2,%3};"
        : "+f"(d[0]), "+f"(d[1]), "+f"(d[2]), "+f"(d[3])
        : "r"(a[0]), "r"(a[1]), "r"(a[2]), "r"(a[3]), "r"(b0), "r"(b1));
}

__device__ __forceinline__ u32 bswz(int brow, int ch) {
    u32 off = (u32)(brow >> 3) * 1024u + (u32)(brow & 7) * 128u + (u32)ch * 16u;
    return off ^ ((u32)(brow & 7) << 4);
}

// ---------------- main kernel ----------------
__global__ void __launch_bounds__(256, 2)
mr_hmma(const float* __restrict__ W, const float* __restrict__ bias,
        float* __restrict__ out)
{
    extern __shared__ __align__(1024) char smem[];
    const u32 sb = smem_u32(smem);
    const int tid  = threadIdx.x;
    const int wid  = tid >> 5;
    const int lane = tid & 31;

    const int jt = blockIdx.x;      // 0..7
    const int b  = blockIdx.y;      // 0..15
    const int di = blockIdx.z;      // 0..9
    const int d  = 1 << di;

    // ---- stage A [128 j x 112 K] bf16 (overlaid on B region, used once) ----
    for (int e = tid; e < 128 * 56; e += 256) {
        int j  = e / 56;
        int kk = (e - j * 56) * 2;
        u32 val = 0;
        int jg = jt * 128 + j;
        if (jg < 1000 && kk < 108) {
            float2 w2 = *reinterpret_cast<const float2*>(
                W + (size_t)(di * 1000 + jg) * 108 + kk);
            __nv_bfloat162 h = __floats2bfloat162_rn(w2.x, w2.y);
            val = *reinterpret_cast<u32*>(&h);
        }
        *reinterpret_cast<u32*>(smem + j * ASTRIDE + kk * 2) = val;
    }
    __syncthreads();

    // ---- A fragments -> registers (7 k-steps x 4 regs) ----
    u32 afr[7][4];
    {
        u32 abase = sb + (u32)(wid * 16 + (lane & 15)) * ASTRIDE
                  + (u32)(lane >> 4) * 16;
#pragma unroll
        for (int q = 0; q < 7; q++)
            ldsm_x4(afr[q][0], afr[q][1], afr[q][2], afr[q][3], abase + q * 32);
    }
    __syncthreads();   // frags loaded before B region is overwritten

    // ---- precompute staging descriptors (7 slots/thread) ----
    // B rows: hi -> 0..107, lo -> 112..219; rows 108..111 & 220..223 zeroed.
    const uint4* sp[7];
    u32 sd[7];
#pragma unroll
    for (int sx = 0; sx < 7; sx++) {
        int e = tid + (sx << 8);
        bool valid = e < 216 * 8;
        int row = valid ? (e >> 3) : 0;
        int ch  = e & 7;
        bool ishi = row < 108;
        int r2 = ishi ? row : row - 108;
        int c = r2 / 9, k = r2 - c * 9;
        int brow = ishi ? row : row + 4;
        int o0 = PADX + (k - 4) * d + ch * 8;
        int s8 = o0 & 7, p0 = o0 - s8;
        const __nv_bfloat16* base = (ishi ? g_xhi8 : g_xlo8)
            + ((size_t)(s8 * NROWS + b * NCH + c)) * ROWLEN + p0;
        sp[sx] = reinterpret_cast<const uint4*>(base);
        sd[sx] = valid ? bswz(brow, ch) : 0xFFFFFFFFu;
    }

    // ---- zero pad rows (108..111, 220..223) in both buffers ----
    for (int e = tid; e < 128; e += 256) {
        int buf = e >> 6, q = e & 63;
        int rr = q >> 3;
        int brow = (rr < 4) ? (108 + rr) : (216 + rr);
        *reinterpret_cast<uint4*>(smem + (buf ? B1OFF : B0OFF) + bswz(brow, q & 7))
            = make_uint4(0, 0, 0, 0);
    }

    // ---- stage chunk 0 into B0 ----
#pragma unroll
    for (int sx = 0; sx < 7; sx++)
        if (sd[sx] != 0xFFFFFFFFu)
            *reinterpret_cast<uint4*>(smem + B0OFF + sd[sx]) = sp[sx][0];
    __syncthreads();

    // per-lane B ldsm address components
    const int bm = lane >> 3, br = lane & 7;
    const u32 laneA = (u32)(bm & 1) * 1024u + (u32)br * 128u;
    const u32 laneT = (u32)(bm >> 1) * 16u;
    const u32 laneR = (u32)br << 4;

    // epilogue state: warp owns j rows w*16+qd and +8
    const int qd = lane >> 2;
    const int j0w = jt * 128 + wid * 16;
    const int jr0 = j0w + qd, jr1 = j0w + qd + 8;
    const float bv0 = (jr0 < 1000) ? bias[di * 1000 + jr0] : 0.0f;
    const float bv1 = (jr1 < 1000) ? bias[di * 1000 + jr1] : 0.0f;
    float m0 = -CUDART_INF_F, m1 = -CUDART_INF_F;
    int   c0 = 0, c1 = 0;

    for (int i = 0; i < NCHUNK; i++) {
        const u32 bcur = (i & 1) ? B1OFF : B0OFF;

        // stage chunk i+1 into the other buffer (overlaps MMA)
        if (i + 1 < NCHUNK) {
            const u32 bnxt = (i & 1) ? B0OFF : B1OFF;
            const int u4i = (i + 1) << 3;       // (i+1)*64 elems = (i+1)*8 uint4
#pragma unroll
            for (int sx = 0; sx < 7; sx++)
                if (sd[sx] != 0xFFFFFFFFu)
                    *reinterpret_cast<uint4*>(smem + bnxt + sd[sx]) = sp[sx][u4i];
        }

        // compute chunk i: D[16 x 64] per warp
        float dacc[8][4];
#pragma unroll
        for (int p = 0; p < 8; p++) {
            dacc[p][0] = 0.f; dacc[p][1] = 0.f; dacc[p][2] = 0.f; dacc[p][3] = 0.f;
        }
        const u32 bb = sb + bcur + laneA;
#pragma unroll
        for (int q = 0; q < 14; q++) {
            const u32* aq = afr[(q < 7) ? q : q - 7];
#pragma unroll
            for (int p = 0; p < 4; p++) {
                u32 b0, b1, b2, b3;
                ldsm_x4t(b0, b1, b2, b3,
                         bb + (u32)q * 2048u + (((u32)p * 32u + laneT) ^ laneR));
                mma16816(dacc[2 * p],     aq, b0, b1);
                mma16816(dacc[2 * p + 1], aq, b2, b3);
            }
        }

        // fused epilogue (last chunk: only first 8 t valid -> p-tile 0)
        const int ntmax = (i == NCHUNK - 1) ? 1 : 8;
#pragma unroll
        for (int p = 0; p < 8; p++) {
            if (p < ntmax) {
                m0 = fmaxf(m0, fmaxf(dacc[p][0], dacc[p][1]));
                c0 += (dacc[p][0] > bv0) + (dacc[p][1] > bv0);
                m1 = fmaxf(m1, fmaxf(dacc[p][2], dacc[p][3]));
                c1 += (dacc[p][2] > bv1) + (dacc[p][3] > bv1);
            }
        }
        __syncthreads();
    }

    // reduce across the 4 lanes of each quad, write out
#pragma unroll
    for (int o = 1; o < 4; o <<= 1) {
        m0 = fmaxf(m0, __shfl_xor_sync(0xffffffffu, m0, o));
        m1 = fmaxf(m1, __shfl_xor_sync(0xffffffffu, m1, o));
        c0 += __shfl_xor_sync(0xffffffffu, c0, o);
        c1 += __shfl_xor_sync(0xffffffffu, c1, o);
    }
    if ((lane & 3) == 0) {
        float* ob = out + (size_t)b * 20000 + di * 2000;
        if (jr0 < 1000) { ob[jr0] = m0; ob[1000 + jr0] = (float)c0 * (1.0f / LSEQ); }
        if (jr1 < 1000) { ob[jr1] = m1; ob[1000 + jr1] = (float)c1 * (1.0f / LSEQ); }
    }
}

extern "C" void kernel_launch(void* const* d_in, const int* in_sizes, int n_in,
                              void* d_out, int out_size)
{
    const float* x    = (const float*)d_in[0];  // [16,12,5000]
    const float* W    = (const float*)d_in[1];  // [10,1000,12,9]
    const float* bias = (const float*)d_in[2];  // [10,1000]
    float* out = (float*)d_out;                 // [16,20000]

    dim3 pg((ROWLEN / 2 + 255) / 256, NROWS, 8);
    prep_kernel<<<pg, 256>>>(x);

    cudaFuncSetAttribute(mr_hmma, cudaFuncAttributeMaxDynamicSharedMemorySize, SMEMSZ);
    dim3 grid(8, 16, 10);
    mr_hmma<<<grid, 256, SMEMSZ>>>(W, bias, out);
}

// round 7
// speedup vs baseline: 10.9475x; 1.1690x over previous
#include <cuda_runtime.h>
#include <cuda_bf16.h>
#include <cstdint>
#include <math_constants.h>

// MiniRocket via mma.sync (HMMA) bf16 split GEMM, round 7.
// Warp M-tile doubled to 32 (each B-ldsm feeds 4 MMAs -> half the L1 traffic
// per MMA). CTA = 4 warps = 128j x 32t chunk; 3 CTAs/SM (12 warps).
// B layout: 112 smem rows x 128B; hi K-rows in byte 0..63, lo K-rows in 64..127
// of each row; SW128-style XOR swizzle; 14 atoms = 14336B per buffer.

#define LSEQ    5000
#define PADX    2112
#define ROWLEN  9224            // PADX + LSEQ + PADX
#define NCH     12
#define NROWS   192             // 16 batch * 12 ch
#define NCHUNK  157             // ceil(5000/32)
#define ASTRIDE 240             // A row stride bytes (112 bf16 + pad), 16 | 240

#define BSZ     14336           // 14 atoms x 1024B
#define B0OFF   0
#define B1OFF   BSZ
#define SMEMSZ  30720           // A staging region (128*240), covers both B bufs

typedef unsigned u32;

// merged hi/lo, 8 shifts: g_x8[(part*8 + s)*NROWS + row][p] ; part 0=hi, 1=lo
__device__ __align__(16) __nv_bfloat16 g_x8[16 * NROWS * ROWLEN];

// ---------------- prep: padded, hi/lo split, 8 shifts ----------------
__global__ void prep_kernel(const float* __restrict__ x) {
    int p2 = blockIdx.x * 256 + threadIdx.x;
    if (p2 >= ROWLEN / 2) return;
    int row = blockIdx.y;                      // 0..191
    int s   = blockIdx.z;                      // 0..7
    int p   = p2 * 2;

    float v0 = 0.f, v1 = 0.f;
    int i0 = p + s - PADX, i1 = i0 + 1;
    if (i0 >= 0 && i0 < LSEQ) v0 = x[(size_t)row * LSEQ + i0];
    if (i1 >= 0 && i1 < LSEQ) v1 = x[(size_t)row * LSEQ + i1];

    __nv_bfloat16 h0 = __float2bfloat16(v0);
    __nv_bfloat16 h1 = __float2bfloat16(v1);
    __nv_bfloat16 l0 = __float2bfloat16(v0 - __bfloat162float(h0));
    __nv_bfloat16 l1 = __float2bfloat16(v1 - __bfloat162float(h1));

    size_t oh = ((size_t)s * NROWS + row) * ROWLEN + p;
    size_t ol = ((size_t)(8 + s) * NROWS + row) * ROWLEN + p;
    __nv_bfloat162 hh; hh.x = h0; hh.y = h1;
    __nv_bfloat162 ll; ll.x = l0; ll.y = l1;
    *reinterpret_cast<__nv_bfloat162*>(g_x8 + oh) = hh;
    *reinterpret_cast<__nv_bfloat162*>(g_x8 + ol) = ll;
}

// ---------------- PTX helpers (baseline, sm_80+) ----------------
__device__ __forceinline__ u32 smem_u32(const void* p) {
    u32 a;
    asm("{ .reg .u64 t; cvta.to.shared.u64 t, %1; cvt.u32.u64 %0, t; }"
        : "=r"(a) : "l"(p));
    return a;
}
__device__ __forceinline__ void ldsm_x4(u32& r0, u32& r1, u32& r2, u32& r3, u32 a) {
    asm volatile("ldmatrix.sync.aligned.m8n8.x4.shared.b16 {%0,%1,%2,%3}, [%4];"
                 : "=r"(r0), "=r"(r1), "=r"(r2), "=r"(r3) : "r"(a));
}
__device__ __forceinline__ void ldsm_x4t(u32& r0, u32& r1, u32& r2, u32& r3, u32 a) {
    asm volatile("ldmatrix.sync.aligned.m8n8.x4.trans.shared.b16 {%0,%1,%2,%3}, [%4];"
                 : "=r"(r0), "=r"(r1), "=r"(r2), "=r"(r3) : "r"(a));
}
__device__ __forceinline__ void mma16816(float* d, const u32* a, u32 b0, u32 b1) {
    asm volatile(
        "mma.sync.aligned.m16n8k16.row.col.f32.bf16.bf16.f32 "
        "{%0,%1,%2,%3}, {%4,%5,%6,%7}, {%8,%9}, {%0,%1,%2,%3};"
        : "+f"(d[0]), "+f"(d[1]), "+f"(d[2]), "+f"(d[3])
        : "r"(a[0]), "r"(a[1]), "r"(a[2]), "r"(a[3]), "r"(b0), "r"(b1));
}

// ---------------- main kernel ----------------
__global__ void __launch_bounds__(128, 3)
mr_hmma(const float* __restrict__ W, const float* __restrict__ bias,
        float* __restrict__ out)
{
    extern __shared__ __align__(1024) char smem[];
    const u32 sb = smem_u32(smem);
    const int tid  = threadIdx.x;
    const int wid  = tid >> 5;      // 0..3
    const int lane = tid & 31;

    const int jt = blockIdx.x;      // 0..7
    const int b  = blockIdx.y;      // 0..15
    const int di = blockIdx.z;      // 0..9
    const int d  = 1 << di;

    // ---- stage A [128 j x 112 K] bf16 (overlaid; used once) ----
    for (int e = tid; e < 128 * 56; e += 128) {
        int j  = e / 56;
        int kk = (e - j * 56) * 2;
        u32 val = 0;
        int jg = jt * 128 + j;
        if (jg < 1000 && kk < 108) {
            float2 w2 = *reinterpret_cast<const float2*>(
                W + (size_t)(di * 1000 + jg) * 108 + kk);
            __nv_bfloat162 h = __floats2bfloat162_rn(w2.x, w2.y);
            val = *reinterpret_cast<u32*>(&h);
        }
        *reinterpret_cast<u32*>(smem + j * ASTRIDE + kk * 2) = val;
    }
    __syncthreads();

    // ---- A fragments: 7 ksteps x 2 mtiles x 4 regs ----
    u32 afr[7][2][4];
#pragma unroll
    for (int mt = 0; mt < 2; mt++) {
        u32 abase = sb + (u32)(wid * 32 + mt * 16 + (lane & 15)) * ASTRIDE
                  + (u32)(lane >> 4) * 16;
#pragma unroll
        for (int q = 0; q < 7; q++)
            ldsm_x4(afr[q][mt][0], afr[q][mt][1], afr[q][mt][2], afr[q][mt][3],
                    abase + q * 32);
    }
    __syncthreads();   // frags loaded before B region is overwritten

    // ---- staging descriptors: 7 slots/thread (864 valid of 896) ----
    // smem row r2 (0..107 real, 108..111 pad): hi in bytes 0..63, lo 64..127.
    u32 so[7];  // element offset into g_x8
    u32 sd[7];  // swizzled smem byte offset (~0 = invalid)
#pragma unroll
    for (int sx = 0; sx < 7; sx++) {
        int e = tid + (sx << 7);
        bool valid = e < 216 * 4;
        int row = valid ? (e >> 2) : 0;
        int ch  = e & 3;
        bool ishi = row < 108;
        int r2 = ishi ? row : row - 108;
        int c = r2 / 9, k = r2 - c * 9;
        int o0 = PADX + (k - 4) * d + ch * 8;
        int s8 = o0 & 7, p0 = o0 - s8;
        so[sx] = (u32)((((ishi ? 0 : 8) + s8) * NROWS + b * NCH + c) * ROWLEN + p0);
        int rb = r2 & 7;
        u32 off = (u32)(r2 >> 3) * 1024u + (u32)rb * 128u
                + ((u32)(((ishi ? 0 : 4) + ch) ^ rb) * 16u);
        sd[sx] = valid ? off : 0xFFFFFFFFu;
    }

    // ---- zero pad rows 108..111 (both halves, both buffers) ----
    if (tid < 64) {
        int buf = tid >> 5, q = tid & 31;
        int rr = 108 + (q >> 3), c8 = q & 7;
        u32 off = (u32)(rr >> 3) * 1024u + (u32)(rr & 7) * 128u
                + ((u32)(c8 ^ (rr & 7)) * 16u);
        *reinterpret_cast<uint4*>(smem + (buf ? B1OFF : B0OFF) + off)
            = make_uint4(0, 0, 0, 0);
    }

    // ---- stage chunk 0 into B0 ----
#pragma unroll
    for (int sx = 0; sx < 7; sx++)
        if (sd[sx] != 0xFFFFFFFFu)
            *reinterpret_cast<uint4*>(smem + B0OFF + sd[sx])
                = *reinterpret_cast<const uint4*>(g_x8 + so[sx]);
    __syncthreads();

    // ---- per-lane ldsm-B address components ----
    const u32 rb7  = lane & 7;
    const u32 hi8  = (u32)((lane & 15) >> 3);
    const u32 g0   = (u32)(lane >> 4);
    const u32 laneBase = hi8 * 1024u + rb7 * 128u;
    u32 xv[2][2];
#pragma unroll
    for (int h = 0; h < 2; h++)
#pragma unroll
        for (int p = 0; p < 2; p++)
            xv[h][p] = (((u32)(h * 4) + g0 + (u32)(2 * p)) ^ rb7) * 16u;

    // ---- epilogue state: lane owns 4 j rows ----
    const int qd  = lane >> 2;
    const int j0w = jt * 128 + wid * 32;
    int jr[4] = { j0w + qd, j0w + qd + 8, j0w + 16 + qd, j0w + 24 + qd };
    float bv[4], m[4];
    int   cn[4];
#pragma unroll
    for (int r = 0; r < 4; r++) {
        bv[r] = (jr[r] < 1000) ? bias[di * 1000 + jr[r]] : 0.0f;
        m[r]  = -CUDART_INF_F;
        cn[r] = 0;
    }

    for (int i = 0; i < NCHUNK; i++) {
        const u32 bcur = (i & 1) ? B1OFF : B0OFF;
        const u32 bnxt = (i & 1) ? B0OFF : B1OFF;
        const bool pref = (i + 1 < NCHUNK);

        // prefetch chunk i+1 (LDGs issued before the MMA block)
        uint4 v[7];
        if (pref) {
            const u32 u4i = (u32)(i + 1) * 4u;
#pragma unroll
            for (int sx = 0; sx < 7; sx++)
                if (sd[sx] != 0xFFFFFFFFu)
                    v[sx] = reinterpret_cast<const uint4*>(g_x8 + so[sx])[u4i];
        }

        // MMA chunk i: D[32j x 32t] per warp
        float dacc[2][4][4];
#pragma unroll
        for (int mt = 0; mt < 2; mt++)
#pragma unroll
            for (int n = 0; n < 4; n++)
#pragma unroll
                for (int r = 0; r < 4; r++) dacc[mt][n][r] = 0.f;

        const u32 bb = sb + bcur + laneBase;
#pragma unroll
        for (int q = 0; q < 14; q++) {
            const int q7 = (q < 7) ? q : q - 7;
            const int h  = (q < 7) ? 0 : 1;
#pragma unroll
            for (int p = 0; p < 2; p++) {
                u32 b0, b1, b2, b3;
                ldsm_x4t(b0, b1, b2, b3, bb + (u32)q7 * 2048u + xv[h][p]);
                mma16816(dacc[0][2 * p],     afr[q7][0], b0, b1);
                mma16816(dacc[0][2 * p + 1], afr[q7][0], b2, b3);
                mma16816(dacc[1][2 * p],     afr[q7][1], b0, b1);
                mma16816(dacc[1][2 * p + 1], afr[q7][1], b2, b3);
            }
        }

        // store prefetched chunk i+1
        if (pref) {
#pragma unroll
            for (int sx = 0; sx < 7; sx++)
                if (sd[sx] != 0xFFFFFFFFu)
                    *reinterpret_cast<uint4*>(smem + bnxt + sd[sx]) = v[sx];
        }

        // fused epilogue (last chunk: only t 0..7 valid -> ntile 0)
        const int ntmax = (i == NCHUNK - 1) ? 1 : 4;
#pragma unroll
        for (int n = 0; n < 4; n++) {
            if (n < ntmax) {
#pragma unroll
                for (int mt = 0; mt < 2; mt++) {
                    m[2 * mt]     = fmaxf(m[2 * mt],
                                          fmaxf(dacc[mt][n][0], dacc[mt][n][1]));
                    cn[2 * mt]   += (dacc[mt][n][0] > bv[2 * mt])
                                  + (dacc[mt][n][1] > bv[2 * mt]);
                    m[2 * mt + 1] = fmaxf(m[2 * mt + 1],
                                          fmaxf(dacc[mt][n][2], dacc[mt][n][3]));
                    cn[2 * mt + 1] += (dacc[mt][n][2] > bv[2 * mt + 1])
                                    + (dacc[mt][n][3] > bv[2 * mt + 1]);
                }
            }
        }
        __syncthreads();
    }

    // ---- reduce across the 4 lanes of each quad, write out ----
#pragma unroll
    for (int o = 1; o < 4; o <<= 1) {
#pragma unroll
        for (int r = 0; r < 4; r++) {
            m[r]  = fmaxf(m[r], __shfl_xor_sync(0xffffffffu, m[r], o));
            cn[r] += __shfl_xor_sync(0xffffffffu, cn[r], o);
        }
    }
    if ((lane & 3) == 0) {
        float* ob = out + (size_t)b * 20000 + di * 2000;
#pragma unroll
        for (int r = 0; r < 4; r++) {
            if (jr[r] < 1000) {
                ob[jr[r]]        = m[r];
                ob[1000 + jr[r]] = (float)cn[r] * (1.0f / LSEQ);
            }
        }
    }
}

extern "C" void kernel_launch(void* const* d_in, const int* in_sizes, int n_in,
                              void* d_out, int out_size)
{
    const float* x    = (const float*)d_in[0];  // [16,12,5000]
    const float* W    = (const float*)d_in[1];  // [10,1000,12,9]
    const float* bias = (const float*)d_in[2];  // [10,1000]
    float* out = (float*)d_out;                 // [16,20000]

    dim3 pg((ROWLEN / 2 + 255) / 256, NROWS, 8);
    prep_kernel<<<pg, 256>>>(x);

    cudaFuncSetAttribute(mr_hmma, cudaFuncAttributeMaxDynamicSharedMemorySize, SMEMSZ);
    dim3 grid(8, 16, 10);
    mr_hmma<<<grid, 128, SMEMSZ>>>(W, bias, out);
}